// round 1
// baseline (speedup 1.0000x reference)
#include <cuda_runtime.h>
#include <math.h>

#define NSEQ 2048
#define NB 2
#define NH 16
#define DH 64
#define DIM 1024

// Scratch (static __device__ allocation — no cudaMalloc allowed)
__device__ __align__(16) float g_q[NB * NH * NSEQ * DH];
__device__ __align__(16) float g_k[NB * NH * NSEQ * DH];
__device__ __align__(16) float g_v[NB * NH * NSEQ * DH];
__device__ __align__(16) float g_ao[NB * NSEQ * DIM];
__device__ __align__(16) float g_bias[NH * 4096];

// ---------------------------------------------------------------------------
// T5 relative-position bias table: g_bias[h][rel + 2047], rel = j - i
// Faithful replication of the reference bucket math in fp32.
// ---------------------------------------------------------------------------
__global__ void bias_kernel(const float* __restrict__ rel_emb) {
    int idx = blockIdx.x * 256 + threadIdx.x;
    if (idx >= NH * 4096) return;
    int h = idx >> 12;
    int r = idx & 4095;
    int rel = r - 2047;          // rel = k_pos - q_pos
    int n0 = -rel;
    int ret = (n0 < 0) ? 16 : 0;
    int nn = (n0 < 0) ? -n0 : n0;
    int b;
    if (nn < 8) {
        b = nn;
    } else {
        // log(n/8) / log(16) * 8, all fp32, truncate to int (values >= 0)
        float v = logf((float)nn / 8.0f) / (float)2.772588722239781 * 8.0f;
        int vi = 8 + (int)v;
        b = vi < 15 ? vi : 15;
    }
    g_bias[idx] = rel_emb[(ret + b) * NH + h];
}

// ---------------------------------------------------------------------------
// Tiled fp32 GEMM: C[M,N] = A[M,1024] @ B[1024,N], 128x128 tile, 256 thr,
// 8x8 microtile. MODE selects epilogue:
//   0: write q scratch (scaled by d^-0.5 = 0.125, exact) from x@Wq   (N=1024)
//   1: write k,v scratch from x@Wkv                                   (N=2048)
//   2: write out = g_ao@Wo + bo                                       (N=1024)
// ---------------------------------------------------------------------------
template <int MODE>
__global__ __launch_bounds__(256, 2)
void gemm_k(const float* __restrict__ A, const float* __restrict__ B,
            const float* __restrict__ bias, float* __restrict__ out, int N) {
    const int K = 1024;
    __shared__ float As[8][132];   // transposed: As[k][row], pad-132 kills conflicts
    __shared__ float Bs[8][132];   // Bs[k][col]

    int tid = threadIdx.x;
    int row0 = blockIdx.y * 128, col0 = blockIdx.x * 128;
    int arow = tid >> 1, ak = (tid & 1) * 4;
    int brow = tid >> 5, bcol = (tid & 31) * 4;

    const float* Ap = (MODE == 2) ? (const float*)g_ao : A;
    const float* Aptr = Ap + (size_t)(row0 + arow) * K + ak;
    const float* Bptr = B + (size_t)brow * N + col0 + bcol;

    float acc[8][8];
#pragma unroll
    for (int i = 0; i < 8; i++)
#pragma unroll
        for (int j = 0; j < 8; j++) acc[i][j] = 0.f;

    int ty = tid >> 4, tx = tid & 15;

    for (int k0 = 0; k0 < K; k0 += 8) {
        float4 av = *(const float4*)(Aptr + k0);
        float4 bv = *(const float4*)(Bptr + (size_t)k0 * N);
        __syncthreads();
        As[ak + 0][arow] = av.x;
        As[ak + 1][arow] = av.y;
        As[ak + 2][arow] = av.z;
        As[ak + 3][arow] = av.w;
        *(float4*)&Bs[brow][bcol] = bv;
        __syncthreads();
#pragma unroll
        for (int kk = 0; kk < 8; kk++) {
            float a[8], b[8];
            *(float4*)(a)     = *(const float4*)&As[kk][ty * 8];
            *(float4*)(a + 4) = *(const float4*)&As[kk][ty * 8 + 4];
            *(float4*)(b)     = *(const float4*)&Bs[kk][tx * 8];
            *(float4*)(b + 4) = *(const float4*)&Bs[kk][tx * 8 + 4];
#pragma unroll
            for (int i = 0; i < 8; i++)
#pragma unroll
                for (int j = 0; j < 8; j++) acc[i][j] += a[i] * b[j];
        }
    }

#pragma unroll
    for (int i = 0; i < 8; i++) {
        int m = row0 + ty * 8 + i;
        int bb = m >> 11, ii = m & 2047;
#pragma unroll
        for (int j = 0; j < 8; j++) {
            int c = col0 + tx * 8 + j;
            float v = acc[i][j];
            if (MODE == 0) {
                g_q[((size_t)((bb << 4) + (c >> 6)) * NSEQ + ii) * DH + (c & 63)] = v * 0.125f;
            } else if (MODE == 1) {
                if (c < 1024) {
                    g_k[((size_t)((bb << 4) + (c >> 6)) * NSEQ + ii) * DH + (c & 63)] = v;
                } else {
                    int c2 = c - 1024;
                    g_v[((size_t)((bb << 4) + (c2 >> 6)) * NSEQ + ii) * DH + (c2 & 63)] = v;
                }
            } else {
                out[(size_t)m * DIM + c] = v + bias[c];
            }
        }
    }
}

// ---------------------------------------------------------------------------
// Flash attention, fp32. One CTA = one (batch, head, 64-row q-block).
// 256 threads = 16x16 lane grid, 4x4 microtile for both S (64x64) and O (64x64).
// Online softmax with 16-lane shfl row reductions. T5 bias added to logits.
// ---------------------------------------------------------------------------
__global__ __launch_bounds__(256)
void attn_kernel() {
    extern __shared__ float sm[];
    float* Qs     = sm;                // [64][68]  (r-major [r][t])
    float* Kts    = sm + 64 * 68;      // [t][c]    (transposed)
    float* Vs     = sm + 2 * 64 * 68;  // [j][c]
    float* Ps     = sm + 3 * 64 * 68;  // [r][j]
    float* bias_s = sm + 4 * 64 * 68;  // [128]

    int tid = threadIdx.x;
    int i0 = blockIdx.x * 64;
    int h = blockIdx.y;
    int bb = blockIdx.z;
    int ty = tid >> 4, tx = tid & 15;
    int ty4 = ty * 4, tx4 = tx * 4;

    size_t base = ((size_t)(bb * NH + h)) * NSEQ * DH;
    int lrow = tid >> 4;        // 0..15
    int lt4 = (tid & 15) * 4;   // 0..60

    // Load Q tile (scale already folded into g_q)
#pragma unroll
    for (int p = 0; p < 4; p++) {
        int r = p * 16 + lrow;
        float4 q = *(const float4*)&g_q[base + (size_t)(i0 + r) * DH + lt4];
        *(float4*)&Qs[r * 68 + lt4] = q;
    }

    float O[4][4];
    float m_run[4], l_run[4];
#pragma unroll
    for (int r = 0; r < 4; r++) {
        m_run[r] = -1e30f;
        l_run[r] = 0.f;
#pragma unroll
        for (int c = 0; c < 4; c++) O[r][c] = 0.f;
    }

    for (int j0 = 0; j0 < NSEQ; j0 += 64) {
        float4 kvr[4], vvr[4];
#pragma unroll
        for (int p = 0; p < 4; p++) {
            int r = p * 16 + lrow;
            kvr[p] = *(const float4*)&g_k[base + (size_t)(j0 + r) * DH + lt4];
            vvr[p] = *(const float4*)&g_v[base + (size_t)(j0 + r) * DH + lt4];
        }
        __syncthreads();  // previous GEMM2 done reading Kts/Vs/Ps
#pragma unroll
        for (int p = 0; p < 4; p++) {
            int r = p * 16 + lrow;
            Kts[(lt4 + 0) * 68 + r] = kvr[p].x;
            Kts[(lt4 + 1) * 68 + r] = kvr[p].y;
            Kts[(lt4 + 2) * 68 + r] = kvr[p].z;
            Kts[(lt4 + 3) * 68 + r] = kvr[p].w;
            *(float4*)&Vs[r * 68 + lt4] = vvr[p];
        }
        if (tid < 127) bias_s[tid] = g_bias[h * 4096 + (j0 - i0) + 2047 + tid - 63];
        __syncthreads();

        // GEMM1: S = Q K^T  (64x64x64)
        float S[4][4];
#pragma unroll
        for (int r = 0; r < 4; r++)
#pragma unroll
            for (int c = 0; c < 4; c++) S[r][c] = 0.f;
#pragma unroll 8
        for (int t = 0; t < 64; t++) {
            float4 b = *(const float4*)&Kts[t * 68 + tx4];
#pragma unroll
            for (int r = 0; r < 4; r++) {
                float a = Qs[(ty4 + r) * 68 + t];
                S[r][0] += a * b.x;
                S[r][1] += a * b.y;
                S[r][2] += a * b.z;
                S[r][3] += a * b.w;
            }
        }

        // bias + online softmax
#pragma unroll
        for (int r = 0; r < 4; r++) {
#pragma unroll
            for (int c = 0; c < 4; c++)
                S[r][c] += bias_s[(tx4 + c) - (ty4 + r) + 63];
            float mb = fmaxf(fmaxf(S[r][0], S[r][1]), fmaxf(S[r][2], S[r][3]));
#pragma unroll
            for (int o = 1; o < 16; o <<= 1)
                mb = fmaxf(mb, __shfl_xor_sync(0xffffffffu, mb, o));
            float mn = fmaxf(m_run[r], mb);
            float alpha = __expf(m_run[r] - mn);
            m_run[r] = mn;
            float rs = 0.f;
#pragma unroll
            for (int c = 0; c < 4; c++) {
                S[r][c] = __expf(S[r][c] - mn);
                rs += S[r][c];
            }
#pragma unroll
            for (int o = 1; o < 16; o <<= 1)
                rs += __shfl_xor_sync(0xffffffffu, rs, o);
            l_run[r] = l_run[r] * alpha + rs;
#pragma unroll
            for (int c = 0; c < 4; c++) O[r][c] *= alpha;
            float4 p4 = make_float4(S[r][0], S[r][1], S[r][2], S[r][3]);
            *(float4*)&Ps[(ty4 + r) * 68 + tx4] = p4;
        }
        __syncthreads();

        // GEMM2: O += P V  (64x64x64)
#pragma unroll 8
        for (int j = 0; j < 64; j++) {
            float4 b = *(const float4*)&Vs[j * 68 + tx4];
#pragma unroll
            for (int r = 0; r < 4; r++) {
                float a = Ps[(ty4 + r) * 68 + j];
                O[r][0] += a * b.x;
                O[r][1] += a * b.y;
                O[r][2] += a * b.z;
                O[r][3] += a * b.w;
            }
        }
    }

    // epilogue: normalize and write to g_ao in (b, n, h*d) layout
#pragma unroll
    for (int r = 0; r < 4; r++) {
        float inv = 1.0f / l_run[r];
        float4 o = make_float4(O[r][0] * inv, O[r][1] * inv, O[r][2] * inv, O[r][3] * inv);
        int m = i0 + ty4 + r;
        *(float4*)&g_ao[((size_t)(bb * NSEQ + m)) * DIM + h * DH + tx4] = o;
    }
}

// ---------------------------------------------------------------------------
// Launch: bias table -> q proj -> kv proj -> flash attention -> out proj
// ---------------------------------------------------------------------------
extern "C" void kernel_launch(void* const* d_in, const int* in_sizes, int n_in,
                              void* d_out, int out_size) {
    const float* x       = (const float*)d_in[0];
    const float* Wq      = (const float*)d_in[1];
    const float* Wkv     = (const float*)d_in[2];
    const float* Wo      = (const float*)d_in[3];
    const float* bo      = (const float*)d_in[4];
    const float* rel_emb = (const float*)d_in[5];
    float* out = (float*)d_out;

    bias_kernel<<<(NH * 4096 + 255) / 256, 256>>>(rel_emb);

    dim3 blk(256);
    gemm_k<0><<<dim3(1024 / 128, 4096 / 128), blk>>>(x, Wq, nullptr, nullptr, 1024);
    gemm_k<1><<<dim3(2048 / 128, 4096 / 128), blk>>>(x, Wkv, nullptr, nullptr, 2048);

    int smem_bytes = (4 * 64 * 68 + 128) * (int)sizeof(float);  // 70,144 B
    cudaFuncSetAttribute(attn_kernel, cudaFuncAttributeMaxDynamicSharedMemorySize,
                         smem_bytes);
    attn_kernel<<<dim3(NSEQ / 64, NH, NB), blk, smem_bytes>>>();

    gemm_k<2><<<dim3(1024 / 128, 4096 / 128), blk>>>(nullptr, Wo, bo, out, 1024);
}

// round 2
// speedup vs baseline: 1.0110x; 1.0110x over previous
#include <cuda_runtime.h>
#include <math.h>

#define NSEQ 2048
#define NB 2
#define NH 16
#define DH 64
#define DIM 1024

// Scratch (static __device__ allocation — no cudaMalloc allowed)
__device__ __align__(16) float g_q[NB * NH * NSEQ * DH];
__device__ __align__(16) float g_k[NB * NH * NSEQ * DH];
__device__ __align__(16) float g_v[NB * NH * NSEQ * DH];
__device__ __align__(16) float g_ao[NB * NSEQ * DIM];
__device__ __align__(16) float g_bias[NH * 4096];

// ---------------------------------------------------------------------------
// Packed f32x2 helpers (FFMA2 path — 2 fp32 FMAs per issue slot, bit-identical
// rounding to scalar FFMA).
// ---------------------------------------------------------------------------
typedef unsigned long long u64;

__device__ __forceinline__ u64 pk2(float lo, float hi) {
    u64 d;
    asm("mov.b64 %0, {%1, %2};" : "=l"(d) : "f"(lo), "f"(hi));
    return d;
}
__device__ __forceinline__ void upk2(u64 d, float& lo, float& hi) {
    asm("mov.b64 {%0, %1}, %2;" : "=f"(lo), "=f"(hi) : "l"(d));
}
__device__ __forceinline__ void ffma2(u64& d, u64 a, u64 b) {
    asm("fma.rn.f32x2 %0, %1, %2, %0;" : "+l"(d) : "l"(a), "l"(b));
}
__device__ __forceinline__ void fmul2(u64& d, u64 a, u64 b) {
    asm("mul.rn.f32x2 %0, %1, %2;" : "=l"(d) : "l"(a), "l"(b));
}

// ---------------------------------------------------------------------------
// T5 relative-position bias table: g_bias[h][rel + 2047], rel = j - i
// ---------------------------------------------------------------------------
__global__ void bias_kernel(const float* __restrict__ rel_emb) {
    int idx = blockIdx.x * 256 + threadIdx.x;
    if (idx >= NH * 4096) return;
    int h = idx >> 12;
    int r = idx & 4095;
    int rel = r - 2047;          // rel = k_pos - q_pos
    int n0 = -rel;
    int ret = (n0 < 0) ? 16 : 0;
    int nn = (n0 < 0) ? -n0 : n0;
    int b;
    if (nn < 8) {
        b = nn;
    } else {
        float v = logf((float)nn / 8.0f) / (float)2.772588722239781 * 8.0f;
        int vi = 8 + (int)v;
        b = vi < 15 ? vi : 15;
    }
    g_bias[idx] = rel_emb[(ret + b) * NH + h];
}

// ---------------------------------------------------------------------------
// Tiled fp32 GEMM with FFMA2 mainloop: C[M,N] = A[M,1024] @ B[1024,N].
// 128x128 tile, 256 thr, 8x8 microtile packed as 8x(4 pairs).
// ---------------------------------------------------------------------------
template <int MODE>
__global__ __launch_bounds__(256, 2)
void gemm_k(const float* __restrict__ A, const float* __restrict__ B,
            const float* __restrict__ bias, float* __restrict__ out, int N) {
    const int K = 1024;
    __shared__ float As[8][132];   // transposed: As[k][row]
    __shared__ float Bs[8][132];   // Bs[k][col]

    int tid = threadIdx.x;
    int row0 = blockIdx.y * 128, col0 = blockIdx.x * 128;
    int arow = tid >> 1, ak = (tid & 1) * 4;
    int brow = tid >> 5, bcol = (tid & 31) * 4;

    const float* Ap = (MODE == 2) ? (const float*)g_ao : A;
    const float* Aptr = Ap + (size_t)(row0 + arow) * K + ak;
    const float* Bptr = B + (size_t)brow * N + col0 + bcol;

    u64 acc[8][4];
#pragma unroll
    for (int i = 0; i < 8; i++)
#pragma unroll
        for (int j = 0; j < 4; j++) acc[i][j] = 0ULL;   // (0.f, 0.f)

    int ty = tid >> 4, tx = tid & 15;

    for (int k0 = 0; k0 < K; k0 += 8) {
        float4 av = *(const float4*)(Aptr + k0);
        float4 bv = *(const float4*)(Bptr + (size_t)k0 * N);
        __syncthreads();
        As[ak + 0][arow] = av.x;
        As[ak + 1][arow] = av.y;
        As[ak + 2][arow] = av.z;
        As[ak + 3][arow] = av.w;
        *(float4*)&Bs[brow][bcol] = bv;
        __syncthreads();
#pragma unroll
        for (int kk = 0; kk < 8; kk++) {
            float a[8];
            *(float4*)(a)     = *(const float4*)&As[kk][ty * 8];
            *(float4*)(a + 4) = *(const float4*)&As[kk][ty * 8 + 4];
            ulonglong2 b0 = *(const ulonglong2*)&Bs[kk][tx * 8];
            ulonglong2 b1 = *(const ulonglong2*)&Bs[kk][tx * 8 + 4];
            u64 bp[4] = {b0.x, b0.y, b1.x, b1.y};
#pragma unroll
            for (int i = 0; i < 8; i++) {
                u64 ad = pk2(a[i], a[i]);
#pragma unroll
                for (int j = 0; j < 4; j++) ffma2(acc[i][j], ad, bp[j]);
            }
        }
    }

#pragma unroll
    for (int i = 0; i < 8; i++) {
        int m = row0 + ty * 8 + i;
        int bb = m >> 11, ii = m & 2047;
        float cv[8];
#pragma unroll
        for (int j = 0; j < 4; j++) upk2(acc[i][j], cv[2 * j], cv[2 * j + 1]);
#pragma unroll
        for (int j = 0; j < 8; j++) {
            int c = col0 + tx * 8 + j;
            float v = cv[j];
            if (MODE == 0) {
                g_q[((size_t)((bb << 4) + (c >> 6)) * NSEQ + ii) * DH + (c & 63)] = v * 0.125f;
            } else if (MODE == 1) {
                if (c < 1024) {
                    g_k[((size_t)((bb << 4) + (c >> 6)) * NSEQ + ii) * DH + (c & 63)] = v;
                } else {
                    int c2 = c - 1024;
                    g_v[((size_t)((bb << 4) + (c2 >> 6)) * NSEQ + ii) * DH + (c2 & 63)] = v;
                }
            } else {
                out[(size_t)m * DIM + c] = v + bias[c];
            }
        }
    }
}

// ---------------------------------------------------------------------------
// Flash attention, fp32 with FFMA2 mainloops. One CTA = (batch, head, 64 rows).
// 256 threads = 16x16 grid, 4x4 microtile packed as 4x(2 pairs).
// ---------------------------------------------------------------------------
__global__ __launch_bounds__(256)
void attn_kernel() {
    extern __shared__ float sm[];
    float* Qst    = sm;                // [t][r] transposed, stride 68
    float* Kts    = sm + 64 * 68;      // [t][c] transposed
    float* Vs     = sm + 2 * 64 * 68;  // [j][c]
    float* Ps     = sm + 3 * 64 * 68;  // [r][j]
    float* bias_s = sm + 4 * 64 * 68;  // [128]

    int tid = threadIdx.x;
    int i0 = blockIdx.x * 64;
    int h = blockIdx.y;
    int bb = blockIdx.z;
    int ty = tid >> 4, tx = tid & 15;
    int ty4 = ty * 4, tx4 = tx * 4;

    size_t base = ((size_t)(bb * NH + h)) * NSEQ * DH;
    int lrow = tid >> 4;        // 0..15
    int lt4 = (tid & 15) * 4;   // 0..60

    // Load Q tile, store TRANSPOSED (Qst[t][r]) for vectorized a-fetch in GEMM1
#pragma unroll
    for (int p = 0; p < 4; p++) {
        int r = p * 16 + lrow;
        float4 q = *(const float4*)&g_q[base + (size_t)(i0 + r) * DH + lt4];
        Qst[(lt4 + 0) * 68 + r] = q.x;
        Qst[(lt4 + 1) * 68 + r] = q.y;
        Qst[(lt4 + 2) * 68 + r] = q.z;
        Qst[(lt4 + 3) * 68 + r] = q.w;
    }

    u64 O2[4][2];
    float m_run[4], l_run[4];
#pragma unroll
    for (int r = 0; r < 4; r++) {
        m_run[r] = -1e30f;
        l_run[r] = 0.f;
        O2[r][0] = 0ULL;
        O2[r][1] = 0ULL;
    }

    for (int j0 = 0; j0 < NSEQ; j0 += 64) {
        float4 kvr[4], vvr[4];
#pragma unroll
        for (int p = 0; p < 4; p++) {
            int r = p * 16 + lrow;
            kvr[p] = *(const float4*)&g_k[base + (size_t)(j0 + r) * DH + lt4];
            vvr[p] = *(const float4*)&g_v[base + (size_t)(j0 + r) * DH + lt4];
        }
        __syncthreads();  // previous GEMM2 done reading Vs/Ps (and Qst settled)
#pragma unroll
        for (int p = 0; p < 4; p++) {
            int r = p * 16 + lrow;
            Kts[(lt4 + 0) * 68 + r] = kvr[p].x;
            Kts[(lt4 + 1) * 68 + r] = kvr[p].y;
            Kts[(lt4 + 2) * 68 + r] = kvr[p].z;
            Kts[(lt4 + 3) * 68 + r] = kvr[p].w;
            *(float4*)&Vs[r * 68 + lt4] = vvr[p];
        }
        if (tid < 127) bias_s[tid] = g_bias[h * 4096 + (j0 - i0) + 2047 + tid - 63];
        __syncthreads();

        // GEMM1: S = Q K^T  (64x64x64), FFMA2
        u64 S2[4][2];
#pragma unroll
        for (int r = 0; r < 4; r++) { S2[r][0] = 0ULL; S2[r][1] = 0ULL; }
#pragma unroll 8
        for (int t = 0; t < 64; t++) {
            float4 a4 = *(const float4*)&Qst[t * 68 + ty4];      // broadcast over tx
            ulonglong2 bb2 = *(const ulonglong2*)&Kts[t * 68 + tx4];
            u64 ad0 = pk2(a4.x, a4.x);
            u64 ad1 = pk2(a4.y, a4.y);
            u64 ad2 = pk2(a4.z, a4.z);
            u64 ad3 = pk2(a4.w, a4.w);
            ffma2(S2[0][0], ad0, bb2.x); ffma2(S2[0][1], ad0, bb2.y);
            ffma2(S2[1][0], ad1, bb2.x); ffma2(S2[1][1], ad1, bb2.y);
            ffma2(S2[2][0], ad2, bb2.x); ffma2(S2[2][1], ad2, bb2.y);
            ffma2(S2[3][0], ad3, bb2.x); ffma2(S2[3][1], ad3, bb2.y);
        }

        // bias + online softmax (scalar, unpacked)
#pragma unroll
        for (int r = 0; r < 4; r++) {
            float S[4];
            upk2(S2[r][0], S[0], S[1]);
            upk2(S2[r][1], S[2], S[3]);
#pragma unroll
            for (int c = 0; c < 4; c++)
                S[c] += bias_s[(tx4 + c) - (ty4 + r) + 63];
            float mb = fmaxf(fmaxf(S[0], S[1]), fmaxf(S[2], S[3]));
#pragma unroll
            for (int o = 1; o < 16; o <<= 1)
                mb = fmaxf(mb, __shfl_xor_sync(0xffffffffu, mb, o));
            float mn = fmaxf(m_run[r], mb);
            float alpha = __expf(m_run[r] - mn);
            m_run[r] = mn;
            float rs = 0.f;
#pragma unroll
            for (int c = 0; c < 4; c++) {
                S[c] = __expf(S[c] - mn);
                rs += S[c];
            }
#pragma unroll
            for (int o = 1; o < 16; o <<= 1)
                rs += __shfl_xor_sync(0xffffffffu, rs, o);
            l_run[r] = l_run[r] * alpha + rs;
            u64 al2 = pk2(alpha, alpha);
            fmul2(O2[r][0], O2[r][0], al2);
            fmul2(O2[r][1], O2[r][1], al2);
            *(float4*)&Ps[(ty4 + r) * 68 + tx4] = make_float4(S[0], S[1], S[2], S[3]);
        }
        __syncthreads();

        // GEMM2: O += P V  (64x64x64), FFMA2, j unrolled by 4
#pragma unroll 4
        for (int j4 = 0; j4 < 16; j4++) {
            int j = j4 * 4;
            float a_[4][4];
#pragma unroll
            for (int r = 0; r < 4; r++)
                *(float4*)&a_[r][0] = *(const float4*)&Ps[(ty4 + r) * 68 + j]; // bcast
#pragma unroll
            for (int jj = 0; jj < 4; jj++) {
                ulonglong2 bb2 = *(const ulonglong2*)&Vs[(j + jj) * 68 + tx4];
                u64 ad0 = pk2(a_[0][jj], a_[0][jj]);
                u64 ad1 = pk2(a_[1][jj], a_[1][jj]);
                u64 ad2 = pk2(a_[2][jj], a_[2][jj]);
                u64 ad3 = pk2(a_[3][jj], a_[3][jj]);
                ffma2(O2[0][0], ad0, bb2.x); ffma2(O2[0][1], ad0, bb2.y);
                ffma2(O2[1][0], ad1, bb2.x); ffma2(O2[1][1], ad1, bb2.y);
                ffma2(O2[2][0], ad2, bb2.x); ffma2(O2[2][1], ad2, bb2.y);
                ffma2(O2[3][0], ad3, bb2.x); ffma2(O2[3][1], ad3, bb2.y);
            }
        }
    }

    // epilogue: normalize and write to g_ao in (b, n, h*d) layout
#pragma unroll
    for (int r = 0; r < 4; r++) {
        float inv = 1.0f / l_run[r];
        float o0, o1, o2, o3;
        upk2(O2[r][0], o0, o1);
        upk2(O2[r][1], o2, o3);
        float4 o = make_float4(o0 * inv, o1 * inv, o2 * inv, o3 * inv);
        int m = i0 + ty4 + r;
        *(float4*)&g_ao[((size_t)(bb * NSEQ + m)) * DIM + h * DH + tx4] = o;
    }
}

// ---------------------------------------------------------------------------
// Launch: bias table -> q proj -> kv proj -> flash attention -> out proj
// ---------------------------------------------------------------------------
extern "C" void kernel_launch(void* const* d_in, const int* in_sizes, int n_in,
                              void* d_out, int out_size) {
    const float* x       = (const float*)d_in[0];
    const float* Wq      = (const float*)d_in[1];
    const float* Wkv     = (const float*)d_in[2];
    const float* Wo      = (const float*)d_in[3];
    const float* bo      = (const float*)d_in[4];
    const float* rel_emb = (const float*)d_in[5];
    float* out = (float*)d_out;

    bias_kernel<<<(NH * 4096 + 255) / 256, 256>>>(rel_emb);

    dim3 blk(256);
    gemm_k<0><<<dim3(1024 / 128, 4096 / 128), blk>>>(x, Wq, nullptr, nullptr, 1024);
    gemm_k<1><<<dim3(2048 / 128, 4096 / 128), blk>>>(x, Wkv, nullptr, nullptr, 2048);

    int smem_bytes = (4 * 64 * 68 + 128) * (int)sizeof(float);  // 70,144 B
    cudaFuncSetAttribute(attn_kernel, cudaFuncAttributeMaxDynamicSharedMemorySize,
                         smem_bytes);
    attn_kernel<<<dim3(NSEQ / 64, NH, NB), blk, smem_bytes>>>();

    gemm_k<2><<<dim3(1024 / 128, 4096 / 128), blk>>>(nullptr, Wo, bo, out, 1024);
}

// round 7
// speedup vs baseline: 1.0613x; 1.0497x over previous
#include <cuda_runtime.h>
#include <cuda_bf16.h>
#include <math.h>
#include <stdint.h>

#define NSEQ 2048
#define NB 2
#define NH 16
#define DH 64
#define DIM 1024

// Scratch (static __device__ — no cudaMalloc allowed)
__device__ __align__(16) float g_q[NB * NH * NSEQ * DH];
__device__ __align__(16) float g_k[NB * NH * NSEQ * DH];
__device__ __align__(16) float g_v[NB * NH * NSEQ * DH];
__device__ __align__(16) float g_ao[NB * NSEQ * DIM];
__device__ __align__(16) float g_bias[NH * 4096];

// ---------------------------------------------------------------------------
// FFMA2 helpers (proven)
// ---------------------------------------------------------------------------
typedef unsigned long long u64;
__device__ __forceinline__ u64 pk2(float lo, float hi) {
    u64 d; asm("mov.b64 %0, {%1, %2};" : "=l"(d) : "f"(lo), "f"(hi)); return d;
}
__device__ __forceinline__ void upk2(u64 d, float& lo, float& hi) {
    asm("mov.b64 {%0, %1}, %2;" : "=f"(lo), "=f"(hi) : "l"(d));
}
__device__ __forceinline__ void ffma2(u64& d, u64 a, u64 b) {
    asm("fma.rn.f32x2 %0, %1, %2, %0;" : "+l"(d) : "l"(a), "l"(b));
}
__device__ __forceinline__ void fmul2(u64& d, u64 a, u64 b) {
    asm("mul.rn.f32x2 %0, %1, %2;" : "=l"(d) : "l"(a), "l"(b));
}

// ---------------------------------------------------------------------------
// mma.sync m16n8k16 bf16 + inline hi/lo split helpers
// ---------------------------------------------------------------------------
__device__ __forceinline__ void mma_bf16(float* c, const uint32_t* a, const uint32_t* b) {
    asm volatile(
        "mma.sync.aligned.m16n8k16.row.col.f32.bf16.bf16.f32 "
        "{%0,%1,%2,%3}, {%4,%5,%6,%7}, {%8,%9}, {%0,%1,%2,%3};"
        : "+f"(c[0]), "+f"(c[1]), "+f"(c[2]), "+f"(c[3])
        : "r"(a[0]), "r"(a[1]), "r"(a[2]), "r"(a[3]), "r"(b[0]), "r"(b[1]));
}
__device__ __forceinline__ uint32_t pack_bf2(__nv_bfloat16 a, __nv_bfloat16 b) {
    uint16_t ua = *(uint16_t*)&a, ub = *(uint16_t*)&b;
    return (uint32_t)ua | ((uint32_t)ub << 16);   // element0 (lower k) in low bits
}
// split two fp32 values (k, k+1) into packed bf16x2 hi and lo registers
__device__ __forceinline__ void split2(float x, float y, uint32_t& hi, uint32_t& lo) {
    __nv_bfloat16 hx = __float2bfloat16(x);
    __nv_bfloat16 hy = __float2bfloat16(y);
    __nv_bfloat16 lx = __float2bfloat16(x - __bfloat162float(hx));
    __nv_bfloat16 ly = __float2bfloat16(y - __bfloat162float(hy));
    hi = pack_bf2(hx, hy);
    lo = pack_bf2(lx, ly);
}

// ---------------------------------------------------------------------------
// T5 relative-position bias table (proven)
// ---------------------------------------------------------------------------
__global__ void bias_kernel(const float* __restrict__ rel_emb) {
    int idx = blockIdx.x * 256 + threadIdx.x;
    if (idx >= NH * 4096) return;
    int h = idx >> 12;
    int r = idx & 4095;
    int rel = r - 2047;
    int n0 = -rel;
    int ret = (n0 < 0) ? 16 : 0;
    int nn = (n0 < 0) ? -n0 : n0;
    int b;
    if (nn < 8) {
        b = nn;
    } else {
        float v = logf((float)nn / 8.0f) / (float)2.772588722239781 * 8.0f;
        int vi = 8 + (int)v;
        b = vi < 15 ? vi : 15;
    }
    g_bias[idx] = rel_emb[(ret + b) * NH + h];
}

// ---------------------------------------------------------------------------
// PROVEN FFMA2 GEMM (R2): C[M,N] = A[M,1024] @ B[1024,N]
// MODE 0: q scratch (x@Wq * 0.125)   MODE 1: k,v scratch (x@Wkv)
// ---------------------------------------------------------------------------
template <int MODE>
__global__ __launch_bounds__(256, 2)
void gemm_k(const float* __restrict__ A, const float* __restrict__ B,
            const float* __restrict__ bias, float* __restrict__ out, int N) {
    const int K = 1024;
    __shared__ float As[8][132];
    __shared__ float Bs[8][132];

    int tid = threadIdx.x;
    int row0 = blockIdx.y * 128, col0 = blockIdx.x * 128;
    int arow = tid >> 1, ak = (tid & 1) * 4;
    int brow = tid >> 5, bcol = (tid & 31) * 4;

    const float* Ap = (MODE == 2) ? (const float*)g_ao : A;
    const float* Aptr = Ap + (size_t)(row0 + arow) * K + ak;
    const float* Bptr = B + (size_t)brow * N + col0 + bcol;

    u64 acc[8][4];
#pragma unroll
    for (int i = 0; i < 8; i++)
#pragma unroll
        for (int j = 0; j < 4; j++) acc[i][j] = 0ULL;

    int ty = tid >> 4, tx = tid & 15;

    for (int k0 = 0; k0 < K; k0 += 8) {
        float4 av = *(const float4*)(Aptr + k0);
        float4 bv = *(const float4*)(Bptr + (size_t)k0 * N);
        __syncthreads();
        As[ak + 0][arow] = av.x;
        As[ak + 1][arow] = av.y;
        As[ak + 2][arow] = av.z;
        As[ak + 3][arow] = av.w;
        *(float4*)&Bs[brow][bcol] = bv;
        __syncthreads();
#pragma unroll
        for (int kk = 0; kk < 8; kk++) {
            float a[8];
            *(float4*)(a)     = *(const float4*)&As[kk][ty * 8];
            *(float4*)(a + 4) = *(const float4*)&As[kk][ty * 8 + 4];
            ulonglong2 b0 = *(const ulonglong2*)&Bs[kk][tx * 8];
            ulonglong2 b1 = *(const ulonglong2*)&Bs[kk][tx * 8 + 4];
            u64 bp[4] = {b0.x, b0.y, b1.x, b1.y};
#pragma unroll
            for (int i = 0; i < 8; i++) {
                u64 ad = pk2(a[i], a[i]);
#pragma unroll
                for (int j = 0; j < 4; j++) ffma2(acc[i][j], ad, bp[j]);
            }
        }
    }

#pragma unroll
    for (int i = 0; i < 8; i++) {
        int m = row0 + ty * 8 + i;
        int bb = m >> 11, ii = m & 2047;
        float cv[8];
#pragma unroll
        for (int j = 0; j < 4; j++) upk2(acc[i][j], cv[2 * j], cv[2 * j + 1]);
#pragma unroll
        for (int j = 0; j < 8; j++) {
            int c = col0 + tx * 8 + j;
            float v = cv[j];
            if (MODE == 0) {
                g_q[((size_t)((bb << 4) + (c >> 6)) * NSEQ + ii) * DH + (c & 63)] = v * 0.125f;
            } else if (MODE == 1) {
                if (c < 1024) {
                    g_k[((size_t)((bb << 4) + (c >> 6)) * NSEQ + ii) * DH + (c & 63)] = v;
                } else {
                    int c2 = c - 1024;
                    g_v[((size_t)((bb << 4) + (c2 >> 6)) * NSEQ + ii) * DH + (c2 & 63)] = v;
                }
            } else {
                out[(size_t)m * DIM + c] = v + bias[c];
            }
        }
    }
}

// ---------------------------------------------------------------------------
// DIAGNOSTIC mma GEMM (out-projection only): out = g_ao @ Wo + bo
// 3-term bf16 hi/lo split done INLINE in registers from fp32 sources.
// No preprocessing kernels, no bf16 scratch, no smem.
// CTA 128x128, 8 warps (2M x 4N of 64x32 warp tiles), K stepped by 16.
// A = g_ao[m][k] fp32 row-major; B = Wo[k][n] fp32 (n contiguous).
// Fragments per PTX ISA m16n8k16: A a0=(gId,2t) a1=(gId+8,2t) a2=(gId,2t+8)
// a3=(gId+8,2t+8); B b0=(k=2t,n=gId) b1=(k=2t+8,n=gId); low bits = lower k.
// ---------------------------------------------------------------------------
__global__ __launch_bounds__(256)
void gemm_mma2(float* __restrict__ out, const float* __restrict__ Wo,
               const float* __restrict__ bo) {
    const int tid = threadIdx.x;
    const int wid = tid >> 5, l = tid & 31;
    const int m0 = blockIdx.y * 128, n0 = blockIdx.x * 128;
    const int wm = wid & 1, wn = wid >> 1;
    const int gId = l >> 2, tig = l & 3;

    const int rA0 = m0 + wm * 64 + gId;   // + mf*16 (+8)
    const int nB0 = n0 + wn * 32 + gId;   // + nf*8

    float C[4][4][4];
#pragma unroll
    for (int a = 0; a < 4; a++)
#pragma unroll
        for (int b = 0; b < 4; b++)
#pragma unroll
            for (int c = 0; c < 4; c++) C[a][b][c] = 0.f;

#pragma unroll 1
    for (int k = 0; k < 1024; k += 16) {
        const int kc = k + 2 * tig;
        uint32_t Ahf[4][4], Alf[4][4];
#pragma unroll
        for (int mf = 0; mf < 4; mf++) {
            const float* Ar0 = g_ao + (size_t)(rA0 + mf * 16) * 1024;
            const float* Ar1 = Ar0 + 8 * 1024;
            float2 v00 = *(const float2*)(Ar0 + kc);
            float2 v10 = *(const float2*)(Ar1 + kc);
            float2 v01 = *(const float2*)(Ar0 + kc + 8);
            float2 v11 = *(const float2*)(Ar1 + kc + 8);
            split2(v00.x, v00.y, Ahf[mf][0], Alf[mf][0]);
            split2(v10.x, v10.y, Ahf[mf][1], Alf[mf][1]);
            split2(v01.x, v01.y, Ahf[mf][2], Alf[mf][2]);
            split2(v11.x, v11.y, Ahf[mf][3], Alf[mf][3]);
        }
        uint32_t Bhf[4][2], Blf[4][2];
#pragma unroll
        for (int nf = 0; nf < 4; nf++) {
            int n = nB0 + nf * 8;
            const float* Bc = Wo + (size_t)kc * 1024 + n;   // row k+2t, col n
            float b00 = Bc[0];           // (k+2t,   n)
            float b01 = Bc[1024];        // (k+2t+1, n)
            float b10 = Bc[8 * 1024];    // (k+2t+8, n)
            float b11 = Bc[9 * 1024];    // (k+2t+9, n)
            split2(b00, b01, Bhf[nf][0], Blf[nf][0]);
            split2(b10, b11, Bhf[nf][1], Blf[nf][1]);
        }
#pragma unroll
        for (int mf = 0; mf < 4; mf++)
#pragma unroll
            for (int nf = 0; nf < 4; nf++) {
                mma_bf16(C[mf][nf], Ahf[mf], Bhf[nf]);
                mma_bf16(C[mf][nf], Ahf[mf], Blf[nf]);
                mma_bf16(C[mf][nf], Alf[mf], Bhf[nf]);
            }
    }

    // Epilogue: C fragment (c0,c1 -> row gId; c2,c3 -> row gId+8), cols 2*tig..
#pragma unroll
    for (int mf = 0; mf < 4; mf++) {
#pragma unroll
        for (int half = 0; half < 2; half++) {
            int m = m0 + wm * 64 + mf * 16 + gId + half * 8;
#pragma unroll
            for (int nf = 0; nf < 4; nf++) {
                int c = n0 + wn * 32 + nf * 8 + tig * 2;
                float v0 = C[mf][nf][half * 2], v1 = C[mf][nf][half * 2 + 1];
                *(float2*)&out[(size_t)m * DIM + c] =
                    make_float2(v0 + bo[c], v1 + bo[c + 1]);
            }
        }
    }
}

// ---------------------------------------------------------------------------
// Flash attention, fp32 FFMA2 (proven R2 version; writes fp32 g_ao)
// ---------------------------------------------------------------------------
__global__ __launch_bounds__(256)
void attn_kernel() {
    extern __shared__ float sm[];
    float* Qst    = sm;                // [t][r] transposed, stride 68
    float* Kts    = sm + 64 * 68;      // [t][c] transposed
    float* Vs     = sm + 2 * 64 * 68;  // [j][c]
    float* Ps     = sm + 3 * 64 * 68;  // [r][j]
    float* bias_s = sm + 4 * 64 * 68;  // [128]

    int tid = threadIdx.x;
    int i0 = blockIdx.x * 64;
    int h = blockIdx.y;
    int bb = blockIdx.z;
    int ty = tid >> 4, tx = tid & 15;
    int ty4 = ty * 4, tx4 = tx * 4;

    size_t base = ((size_t)(bb * NH + h)) * NSEQ * DH;
    int lrow = tid >> 4;
    int lt4 = (tid & 15) * 4;

#pragma unroll
    for (int p = 0; p < 4; p++) {
        int r = p * 16 + lrow;
        float4 q = *(const float4*)&g_q[base + (size_t)(i0 + r) * DH + lt4];
        Qst[(lt4 + 0) * 68 + r] = q.x;
        Qst[(lt4 + 1) * 68 + r] = q.y;
        Qst[(lt4 + 2) * 68 + r] = q.z;
        Qst[(lt4 + 3) * 68 + r] = q.w;
    }

    u64 O2[4][2];
    float m_run[4], l_run[4];
#pragma unroll
    for (int r = 0; r < 4; r++) {
        m_run[r] = -1e30f;
        l_run[r] = 0.f;
        O2[r][0] = 0ULL;
        O2[r][1] = 0ULL;
    }

    for (int j0 = 0; j0 < NSEQ; j0 += 64) {
        float4 kvr[4], vvr[4];
#pragma unroll
        for (int p = 0; p < 4; p++) {
            int r = p * 16 + lrow;
            kvr[p] = *(const float4*)&g_k[base + (size_t)(j0 + r) * DH + lt4];
            vvr[p] = *(const float4*)&g_v[base + (size_t)(j0 + r) * DH + lt4];
        }
        __syncthreads();
#pragma unroll
        for (int p = 0; p < 4; p++) {
            int r = p * 16 + lrow;
            Kts[(lt4 + 0) * 68 + r] = kvr[p].x;
            Kts[(lt4 + 1) * 68 + r] = kvr[p].y;
            Kts[(lt4 + 2) * 68 + r] = kvr[p].z;
            Kts[(lt4 + 3) * 68 + r] = kvr[p].w;
            *(float4*)&Vs[r * 68 + lt4] = vvr[p];
        }
        if (tid < 127) bias_s[tid] = g_bias[h * 4096 + (j0 - i0) + 2047 + tid - 63];
        __syncthreads();

        u64 S2[4][2];
#pragma unroll
        for (int r = 0; r < 4; r++) { S2[r][0] = 0ULL; S2[r][1] = 0ULL; }
#pragma unroll 8
        for (int t = 0; t < 64; t++) {
            float4 a4 = *(const float4*)&Qst[t * 68 + ty4];
            ulonglong2 bb2 = *(const ulonglong2*)&Kts[t * 68 + tx4];
            u64 ad0 = pk2(a4.x, a4.x);
            u64 ad1 = pk2(a4.y, a4.y);
            u64 ad2 = pk2(a4.z, a4.z);
            u64 ad3 = pk2(a4.w, a4.w);
            ffma2(S2[0][0], ad0, bb2.x); ffma2(S2[0][1], ad0, bb2.y);
            ffma2(S2[1][0], ad1, bb2.x); ffma2(S2[1][1], ad1, bb2.y);
            ffma2(S2[2][0], ad2, bb2.x); ffma2(S2[2][1], ad2, bb2.y);
            ffma2(S2[3][0], ad3, bb2.x); ffma2(S2[3][1], ad3, bb2.y);
        }

#pragma unroll
        for (int r = 0; r < 4; r++) {
            float S[4];
            upk2(S2[r][0], S[0], S[1]);
            upk2(S2[r][1], S[2], S[3]);
#pragma unroll
            for (int c = 0; c < 4; c++)
                S[c] += bias_s[(tx4 + c) - (ty4 + r) + 63];
            float mb = fmaxf(fmaxf(S[0], S[1]), fmaxf(S[2], S[3]));
#pragma unroll
            for (int o = 1; o < 16; o <<= 1)
                mb = fmaxf(mb, __shfl_xor_sync(0xffffffffu, mb, o));
            float mn = fmaxf(m_run[r], mb);
            float alpha = __expf(m_run[r] - mn);
            m_run[r] = mn;
            float rs = 0.f;
#pragma unroll
            for (int c = 0; c < 4; c++) {
                S[c] = __expf(S[c] - mn);
                rs += S[c];
            }
#pragma unroll
            for (int o = 1; o < 16; o <<= 1)
                rs += __shfl_xor_sync(0xffffffffu, rs, o);
            l_run[r] = l_run[r] * alpha + rs;
            u64 al2 = pk2(alpha, alpha);
            fmul2(O2[r][0], O2[r][0], al2);
            fmul2(O2[r][1], O2[r][1], al2);
            *(float4*)&Ps[(ty4 + r) * 68 + tx4] = make_float4(S[0], S[1], S[2], S[3]);
        }
        __syncthreads();

#pragma unroll 4
        for (int j4 = 0; j4 < 16; j4++) {
            int j = j4 * 4;
            float a_[4][4];
#pragma unroll
            for (int r = 0; r < 4; r++)
                *(float4*)&a_[r][0] = *(const float4*)&Ps[(ty4 + r) * 68 + j];
#pragma unroll
            for (int jj = 0; jj < 4; jj++) {
                ulonglong2 bb2 = *(const ulonglong2*)&Vs[(j + jj) * 68 + tx4];
                u64 ad0 = pk2(a_[0][jj], a_[0][jj]);
                u64 ad1 = pk2(a_[1][jj], a_[1][jj]);
                u64 ad2 = pk2(a_[2][jj], a_[2][jj]);
                u64 ad3 = pk2(a_[3][jj], a_[3][jj]);
                ffma2(O2[0][0], ad0, bb2.x); ffma2(O2[0][1], ad0, bb2.y);
                ffma2(O2[1][0], ad1, bb2.x); ffma2(O2[1][1], ad1, bb2.y);
                ffma2(O2[2][0], ad2, bb2.x); ffma2(O2[2][1], ad2, bb2.y);
                ffma2(O2[3][0], ad3, bb2.x); ffma2(O2[3][1], ad3, bb2.y);
            }
        }
    }

    // epilogue: normalize and write fp32 to g_ao in (b, n, h*d) layout
#pragma unroll
    for (int r = 0; r < 4; r++) {
        float inv = 1.0f / l_run[r];
        float o0, o1, o2, o3;
        upk2(O2[r][0], o0, o1);
        upk2(O2[r][1], o2, o3);
        float4 o = make_float4(o0 * inv, o1 * inv, o2 * inv, o3 * inv);
        int m = i0 + ty4 + r;
        *(float4*)&g_ao[((size_t)(bb * NSEQ + m)) * DIM + h * DH + tx4] = o;
    }
}

// ---------------------------------------------------------------------------
// Launch
// ---------------------------------------------------------------------------
extern "C" void kernel_launch(void* const* d_in, const int* in_sizes, int n_in,
                              void* d_out, int out_size) {
    const float* x       = (const float*)d_in[0];
    const float* Wq      = (const float*)d_in[1];
    const float* Wkv     = (const float*)d_in[2];
    const float* Wo      = (const float*)d_in[3];
    const float* bo      = (const float*)d_in[4];
    const float* rel_emb = (const float*)d_in[5];
    float* out = (float*)d_out;

    bias_kernel<<<(NH * 4096 + 255) / 256, 256>>>(rel_emb);

    dim3 blk(256);
    gemm_k<0><<<dim3(1024 / 128, 4096 / 128), blk>>>(x, Wq, nullptr, nullptr, 1024);
    gemm_k<1><<<dim3(2048 / 128, 4096 / 128), blk>>>(x, Wkv, nullptr, nullptr, 2048);

    int smem_bytes = (4 * 64 * 68 + 128) * (int)sizeof(float);  // 70,144 B
    cudaFuncSetAttribute(attn_kernel, cudaFuncAttributeMaxDynamicSharedMemorySize,
                         smem_bytes);
    attn_kernel<<<dim3(NSEQ / 64, NH, NB), blk, smem_bytes>>>();

    gemm_mma2<<<dim3(8, 32), blk>>>(out, Wo, bo);
}

// round 9
// speedup vs baseline: 1.2259x; 1.1551x over previous
#include <cuda_runtime.h>
#include <cuda_bf16.h>
#include <math.h>
#include <stdint.h>

#define NSEQ 2048
#define NB 2
#define NH 16
#define DH 64
#define DIM 1024

// Scratch (static __device__ — no cudaMalloc allowed)
__device__ __align__(16) float g_q[NB * NH * NSEQ * DH];
__device__ __align__(16) float g_k[NB * NH * NSEQ * DH];
__device__ __align__(16) float g_v[NB * NH * NSEQ * DH];
__device__ __align__(16) float g_ao[NB * NSEQ * DIM];
__device__ __align__(16) float g_bias[NH * 4096];

// ---------------------------------------------------------------------------
// FFMA2 helpers (attention kernel)
// ---------------------------------------------------------------------------
typedef unsigned long long u64;
__device__ __forceinline__ u64 pk2(float lo, float hi) {
    u64 d; asm("mov.b64 %0, {%1, %2};" : "=l"(d) : "f"(lo), "f"(hi)); return d;
}
__device__ __forceinline__ void upk2(u64 d, float& lo, float& hi) {
    asm("mov.b64 {%0, %1}, %2;" : "=f"(lo), "=f"(hi) : "l"(d));
}
__device__ __forceinline__ void ffma2(u64& d, u64 a, u64 b) {
    asm("fma.rn.f32x2 %0, %1, %2, %0;" : "+l"(d) : "l"(a), "l"(b));
}
__device__ __forceinline__ void fmul2(u64& d, u64 a, u64 b) {
    asm("mul.rn.f32x2 %0, %1, %2;" : "=l"(d) : "l"(a), "l"(b));
}

// ---------------------------------------------------------------------------
// mma.sync m16n8k16 bf16 + inline hi/lo split helpers (proven R7)
// ---------------------------------------------------------------------------
__device__ __forceinline__ void mma_bf16(float* c, const uint32_t* a, const uint32_t* b) {
    asm volatile(
        "mma.sync.aligned.m16n8k16.row.col.f32.bf16.bf16.f32 "
        "{%0,%1,%2,%3}, {%4,%5,%6,%7}, {%8,%9}, {%0,%1,%2,%3};"
        : "+f"(c[0]), "+f"(c[1]), "+f"(c[2]), "+f"(c[3])
        : "r"(a[0]), "r"(a[1]), "r"(a[2]), "r"(a[3]), "r"(b[0]), "r"(b[1]));
}
__device__ __forceinline__ uint32_t pack_bf2(__nv_bfloat16 a, __nv_bfloat16 b) {
    uint16_t ua = *(uint16_t*)&a, ub = *(uint16_t*)&b;
    return (uint32_t)ua | ((uint32_t)ub << 16);   // element0 (lower k) in low bits
}
__device__ __forceinline__ void split2(float x, float y, uint32_t& hi, uint32_t& lo) {
    __nv_bfloat16 hx = __float2bfloat16(x);
    __nv_bfloat16 hy = __float2bfloat16(y);
    __nv_bfloat16 lx = __float2bfloat16(x - __bfloat162float(hx));
    __nv_bfloat16 ly = __float2bfloat16(y - __bfloat162float(hy));
    hi = pack_bf2(hx, hy);
    lo = pack_bf2(lx, ly);
}

// ---------------------------------------------------------------------------
// T5 relative-position bias table (proven)
// ---------------------------------------------------------------------------
__global__ void bias_kernel(const float* __restrict__ rel_emb) {
    int idx = blockIdx.x * 256 + threadIdx.x;
    if (idx >= NH * 4096) return;
    int h = idx >> 12;
    int r = idx & 4095;
    int rel = r - 2047;
    int n0 = -rel;
    int ret = (n0 < 0) ? 16 : 0;
    int nn = (n0 < 0) ? -n0 : n0;
    int b;
    if (nn < 8) {
        b = nn;
    } else {
        float v = logf((float)nn / 8.0f) / (float)2.772588722239781 * 8.0f;
        int vi = 8 + (int)v;
        b = vi < 15 ? vi : 15;
    }
    g_bias[idx] = rel_emb[(ret + b) * NH + h];
}

// ---------------------------------------------------------------------------
// mma.sync split GEMM (proven pattern from R7's gemm_mma2), generalized.
// C[m][n] = A[m][:1024] @ W[:1024][n], 3-term inline bf16 hi/lo split.
// CTA 128x128, 8 warps (2M x 4N of 64x32 warp tiles), K stepped by 16.
// A fp32 row-major (stride 1024); W fp32 [1024 k][N n] (n contiguous).
// MODE 0: A=x,    W=Wq  (N=1024) -> g_q (scaled 0.125)
// MODE 1: A=x,    W=Wkv (N=2048) -> g_k / g_v
// MODE 2: A=g_ao, W=Wo  (N=1024) -> out + bo
// ---------------------------------------------------------------------------
template <int MODE>
__global__ __launch_bounds__(256)
void gemm_mma(const float* __restrict__ A, const float* __restrict__ W,
              float* __restrict__ out, const float* __restrict__ bo) {
    const int N = (MODE == 1) ? 2048 : 1024;
    const int tid = threadIdx.x;
    const int wid = tid >> 5, l = tid & 31;
    const int m0 = blockIdx.y * 128, n0 = blockIdx.x * 128;
    const int wm = wid & 1, wn = wid >> 1;
    const int gId = l >> 2, tig = l & 3;

    const float* Ap = (MODE == 2) ? (const float*)g_ao : A;
    const int rA0 = m0 + wm * 64 + gId;   // + mf*16 (+8)
    const int nB0 = n0 + wn * 32 + gId;   // + nf*8

    float C[4][4][4];
#pragma unroll
    for (int a = 0; a < 4; a++)
#pragma unroll
        for (int b = 0; b < 4; b++)
#pragma unroll
            for (int c = 0; c < 4; c++) C[a][b][c] = 0.f;

#pragma unroll 1
    for (int k = 0; k < 1024; k += 16) {
        const int kc = k + 2 * tig;
        uint32_t Ahf[4][4], Alf[4][4];
#pragma unroll
        for (int mf = 0; mf < 4; mf++) {
            const float* Ar0 = Ap + (size_t)(rA0 + mf * 16) * 1024;
            const float* Ar1 = Ar0 + 8 * 1024;
            float2 v00 = *(const float2*)(Ar0 + kc);
            float2 v10 = *(const float2*)(Ar1 + kc);
            float2 v01 = *(const float2*)(Ar0 + kc + 8);
            float2 v11 = *(const float2*)(Ar1 + kc + 8);
            split2(v00.x, v00.y, Ahf[mf][0], Alf[mf][0]);
            split2(v10.x, v10.y, Ahf[mf][1], Alf[mf][1]);
            split2(v01.x, v01.y, Ahf[mf][2], Alf[mf][2]);
            split2(v11.x, v11.y, Ahf[mf][3], Alf[mf][3]);
        }
        uint32_t Bhf[4][2], Blf[4][2];
#pragma unroll
        for (int nf = 0; nf < 4; nf++) {
            int n = nB0 + nf * 8;
            const float* Bc = W + (size_t)kc * N + n;   // row k+2t, col n
            float b00 = Bc[0];              // (k+2t,   n)
            float b01 = Bc[N];              // (k+2t+1, n)
            float b10 = Bc[8 * (size_t)N];  // (k+2t+8, n)
            float b11 = Bc[9 * (size_t)N];  // (k+2t+9, n)
            split2(b00, b01, Bhf[nf][0], Blf[nf][0]);
            split2(b10, b11, Bhf[nf][1], Blf[nf][1]);
        }
#pragma unroll
        for (int mf = 0; mf < 4; mf++)
#pragma unroll
            for (int nf = 0; nf < 4; nf++) {
                mma_bf16(C[mf][nf], Ahf[mf], Bhf[nf]);
                mma_bf16(C[mf][nf], Ahf[mf], Blf[nf]);
                mma_bf16(C[mf][nf], Alf[mf], Bhf[nf]);
            }
    }

    // Epilogue: C fragment (c0,c1 -> row gId; c2,c3 -> row gId+8), cols 2*tig..
#pragma unroll
    for (int mf = 0; mf < 4; mf++) {
#pragma unroll
        for (int half = 0; half < 2; half++) {
            int m = m0 + wm * 64 + mf * 16 + gId + half * 8;
            int bb = m >> 11, ii = m & 2047;
#pragma unroll
            for (int nf = 0; nf < 4; nf++) {
                int c = n0 + wn * 32 + nf * 8 + tig * 2;
                float v0 = C[mf][nf][half * 2], v1 = C[mf][nf][half * 2 + 1];
                if (MODE == 0) {
                    *(float2*)&g_q[((size_t)((bb << 4) + (c >> 6)) * NSEQ + ii) * DH + (c & 63)] =
                        make_float2(v0 * 0.125f, v1 * 0.125f);
                } else if (MODE == 1) {
                    if (c < 1024) {
                        *(float2*)&g_k[((size_t)((bb << 4) + (c >> 6)) * NSEQ + ii) * DH + (c & 63)] =
                            make_float2(v0, v1);
                    } else {
                        int c2 = c - 1024;
                        *(float2*)&g_v[((size_t)((bb << 4) + (c2 >> 6)) * NSEQ + ii) * DH + (c2 & 63)] =
                            make_float2(v0, v1);
                    }
                } else {
                    *(float2*)&out[(size_t)m * DIM + c] =
                        make_float2(v0 + bo[c], v1 + bo[c + 1]);
                }
            }
        }
    }
}

// ---------------------------------------------------------------------------
// Flash attention, fp32 FFMA2 (proven; writes fp32 g_ao)
// ---------------------------------------------------------------------------
__global__ __launch_bounds__(256)
void attn_kernel() {
    extern __shared__ float sm[];
    float* Qst    = sm;                // [t][r] transposed, stride 68
    float* Kts    = sm + 64 * 68;      // [t][c] transposed
    float* Vs     = sm + 2 * 64 * 68;  // [j][c]
    float* Ps     = sm + 3 * 64 * 68;  // [r][j]
    float* bias_s = sm + 4 * 64 * 68;  // [128]

    int tid = threadIdx.x;
    int i0 = blockIdx.x * 64;
    int h = blockIdx.y;
    int bb = blockIdx.z;
    int ty = tid >> 4, tx = tid & 15;
    int ty4 = ty * 4, tx4 = tx * 4;

    size_t base = ((size_t)(bb * NH + h)) * NSEQ * DH;
    int lrow = tid >> 4;
    int lt4 = (tid & 15) * 4;

#pragma unroll
    for (int p = 0; p < 4; p++) {
        int r = p * 16 + lrow;
        float4 q = *(const float4*)&g_q[base + (size_t)(i0 + r) * DH + lt4];
        Qst[(lt4 + 0) * 68 + r] = q.x;
        Qst[(lt4 + 1) * 68 + r] = q.y;
        Qst[(lt4 + 2) * 68 + r] = q.z;
        Qst[(lt4 + 3) * 68 + r] = q.w;
    }

    u64 O2[4][2];
    float m_run[4], l_run[4];
#pragma unroll
    for (int r = 0; r < 4; r++) {
        m_run[r] = -1e30f;
        l_run[r] = 0.f;
        O2[r][0] = 0ULL;
        O2[r][1] = 0ULL;
    }

    for (int j0 = 0; j0 < NSEQ; j0 += 64) {
        float4 kvr[4], vvr[4];
#pragma unroll
        for (int p = 0; p < 4; p++) {
            int r = p * 16 + lrow;
            kvr[p] = *(const float4*)&g_k[base + (size_t)(j0 + r) * DH + lt4];
            vvr[p] = *(const float4*)&g_v[base + (size_t)(j0 + r) * DH + lt4];
        }
        __syncthreads();
#pragma unroll
        for (int p = 0; p < 4; p++) {
            int r = p * 16 + lrow;
            Kts[(lt4 + 0) * 68 + r] = kvr[p].x;
            Kts[(lt4 + 1) * 68 + r] = kvr[p].y;
            Kts[(lt4 + 2) * 68 + r] = kvr[p].z;
            Kts[(lt4 + 3) * 68 + r] = kvr[p].w;
            *(float4*)&Vs[r * 68 + lt4] = vvr[p];
        }
        if (tid < 127) bias_s[tid] = g_bias[h * 4096 + (j0 - i0) + 2047 + tid - 63];
        __syncthreads();

        u64 S2[4][2];
#pragma unroll
        for (int r = 0; r < 4; r++) { S2[r][0] = 0ULL; S2[r][1] = 0ULL; }
#pragma unroll 8
        for (int t = 0; t < 64; t++) {
            float4 a4 = *(const float4*)&Qst[t * 68 + ty4];
            ulonglong2 bb2 = *(const ulonglong2*)&Kts[t * 68 + tx4];
            u64 ad0 = pk2(a4.x, a4.x);
            u64 ad1 = pk2(a4.y, a4.y);
            u64 ad2 = pk2(a4.z, a4.z);
            u64 ad3 = pk2(a4.w, a4.w);
            ffma2(S2[0][0], ad0, bb2.x); ffma2(S2[0][1], ad0, bb2.y);
            ffma2(S2[1][0], ad1, bb2.x); ffma2(S2[1][1], ad1, bb2.y);
            ffma2(S2[2][0], ad2, bb2.x); ffma2(S2[2][1], ad2, bb2.y);
            ffma2(S2[3][0], ad3, bb2.x); ffma2(S2[3][1], ad3, bb2.y);
        }

#pragma unroll
        for (int r = 0; r < 4; r++) {
            float S[4];
            upk2(S2[r][0], S[0], S[1]);
            upk2(S2[r][1], S[2], S[3]);
#pragma unroll
            for (int c = 0; c < 4; c++)
                S[c] += bias_s[(tx4 + c) - (ty4 + r) + 63];
            float mb = fmaxf(fmaxf(S[0], S[1]), fmaxf(S[2], S[3]));
#pragma unroll
            for (int o = 1; o < 16; o <<= 1)
                mb = fmaxf(mb, __shfl_xor_sync(0xffffffffu, mb, o));
            float mn = fmaxf(m_run[r], mb);
            float alpha = __expf(m_run[r] - mn);
            m_run[r] = mn;
            float rs = 0.f;
#pragma unroll
            for (int c = 0; c < 4; c++) {
                S[c] = __expf(S[c] - mn);
                rs += S[c];
            }
#pragma unroll
            for (int o = 1; o < 16; o <<= 1)
                rs += __shfl_xor_sync(0xffffffffu, rs, o);
            l_run[r] = l_run[r] * alpha + rs;
            u64 al2 = pk2(alpha, alpha);
            fmul2(O2[r][0], O2[r][0], al2);
            fmul2(O2[r][1], O2[r][1], al2);
            *(float4*)&Ps[(ty4 + r) * 68 + tx4] = make_float4(S[0], S[1], S[2], S[3]);
        }
        __syncthreads();

#pragma unroll 4
        for (int j4 = 0; j4 < 16; j4++) {
            int j = j4 * 4;
            float a_[4][4];
#pragma unroll
            for (int r = 0; r < 4; r++)
                *(float4*)&a_[r][0] = *(const float4*)&Ps[(ty4 + r) * 68 + j];
#pragma unroll
            for (int jj = 0; jj < 4; jj++) {
                ulonglong2 bb2 = *(const ulonglong2*)&Vs[(j + jj) * 68 + tx4];
                u64 ad0 = pk2(a_[0][jj], a_[0][jj]);
                u64 ad1 = pk2(a_[1][jj], a_[1][jj]);
                u64 ad2 = pk2(a_[2][jj], a_[2][jj]);
                u64 ad3 = pk2(a_[3][jj], a_[3][jj]);
                ffma2(O2[0][0], ad0, bb2.x); ffma2(O2[0][1], ad0, bb2.y);
                ffma2(O2[1][0], ad1, bb2.x); ffma2(O2[1][1], ad1, bb2.y);
                ffma2(O2[2][0], ad2, bb2.x); ffma2(O2[2][1], ad2, bb2.y);
                ffma2(O2[3][0], ad3, bb2.x); ffma2(O2[3][1], ad3, bb2.y);
            }
        }
    }

    // epilogue: normalize and write fp32 to g_ao in (b, n, h*d) layout
#pragma unroll
    for (int r = 0; r < 4; r++) {
        float inv = 1.0f / l_run[r];
        float o0, o1, o2, o3;
        upk2(O2[r][0], o0, o1);
        upk2(O2[r][1], o2, o3);
        float4 o = make_float4(o0 * inv, o1 * inv, o2 * inv, o3 * inv);
        int m = i0 + ty4 + r;
        *(float4*)&g_ao[((size_t)(bb * NSEQ + m)) * DIM + h * DH + tx4] = o;
    }
}

// ---------------------------------------------------------------------------
// Launch
// ---------------------------------------------------------------------------
extern "C" void kernel_launch(void* const* d_in, const int* in_sizes, int n_in,
                              void* d_out, int out_size) {
    const float* x       = (const float*)d_in[0];
    const float* Wq      = (const float*)d_in[1];
    const float* Wkv     = (const float*)d_in[2];
    const float* Wo      = (const float*)d_in[3];
    const float* bo      = (const float*)d_in[4];
    const float* rel_emb = (const float*)d_in[5];
    float* out = (float*)d_out;

    bias_kernel<<<(NH * 4096 + 255) / 256, 256>>>(rel_emb);

    dim3 blk(256);
    gemm_mma<0><<<dim3(8, 32), blk>>>(x, Wq, nullptr, nullptr);
    gemm_mma<1><<<dim3(16, 32), blk>>>(x, Wkv, nullptr, nullptr);

    int smem_bytes = (4 * 64 * 68 + 128) * (int)sizeof(float);  // 70,144 B
    cudaFuncSetAttribute(attn_kernel, cudaFuncAttributeMaxDynamicSharedMemorySize,
                         smem_bytes);
    attn_kernel<<<dim3(NSEQ / 64, NH, NB), blk, smem_bytes>>>();

    gemm_mma<2><<<dim3(8, 32), blk>>>(nullptr, Wo, out, bo);
}